// round 6
// baseline (speedup 1.0000x reference)
#include <cuda_runtime.h>
#include <math.h>
#include <stdint.h>

// Problem constants (fixed by the reference)
#define B_  1024
#define T_  80
#define E_  512
#define U_  512
#define M1  (B_ * T_)   // 81920 rows of the input-projection GEMM

// Static device scratch (allocation-free rule: __device__ globals)
__device__ float g_xk[(size_t)M1 * U_];        // [B*T, U] input projection (+bias)
__device__ float g_h[2][(size_t)B_ * U_];      // ping-pong hidden state

// ---------------------------------------------------------------------------
// Helpers: tf32 split + mma.sync
// ---------------------------------------------------------------------------
__device__ __forceinline__ void split_tf32(float x, uint32_t& hi, uint32_t& lo)
{
    asm("cvt.rna.tf32.f32 %0, %1;" : "=r"(hi) : "f"(x));
    float r = x - __uint_as_float(hi);
    asm("cvt.rna.tf32.f32 %0, %1;" : "=r"(lo) : "f"(r));
}

__device__ __forceinline__ void mma8(float* c, const uint32_t* a, const uint32_t* b)
{
    asm volatile(
        "mma.sync.aligned.m16n8k8.row.col.f32.tf32.tf32.f32 "
        "{%0,%1,%2,%3}, {%4,%5,%6,%7}, {%8,%9}, {%0,%1,%2,%3};"
        : "+f"(c[0]), "+f"(c[1]), "+f"(c[2]), "+f"(c[3])
        : "r"(a[0]), "r"(a[1]), "r"(a[2]), "r"(a[3]), "r"(b[0]), "r"(b[1]));
}

// 3xTF32: d += hi*hi + hi*lo + lo*hi  (drops lo*lo; ~fp32 accuracy)
__device__ __forceinline__ void mma3x(float* c,
                                      const uint32_t* ah, const uint32_t* al,
                                      const uint32_t* bh, const uint32_t* bl)
{
    mma8(c, ah, bl);
    mma8(c, al, bh);
    mma8(c, ah, bh);
}

// Fragment-order SMEM indexing (m16n8k8):
//  A element (r16 in [0,16), c8 in [0,8)) -> lane = (r16&7)*4 + (c8&3),
//    slot = ((r16>>3)&1) | ((c8>>2)<<1)            (matches {a0,a1,a2,a3})
//  B element (k8 in [0,8), n8 in [0,8))  -> lane = n8*4 + (k8&3), slot = k8>>2

// ---------------------------------------------------------------------------
// Kernel 1 (3xTF32 mma): g_xk[m,n] = sum_e emb[tokens[m],e]*W[e,n] + bias[n]
// CTA tile 128x64, BK=8, 256 thr (8 warps, warp tile 32x32), double-buffered.
// ---------------------------------------------------------------------------
__global__ void __launch_bounds__(256)
gemm_embed_mma(const int* __restrict__ tokens,
               const float* __restrict__ emb,
               const float* __restrict__ W,
               const float* __restrict__ bias)
{
    __shared__ uint32_t As_h[2][8][32][4];  // [buf][mfrag][lane][slot]
    __shared__ uint32_t As_l[2][8][32][4];
    __shared__ uint32_t Bs_h[2][8][32][2];  // [buf][nfrag][lane][slot]
    __shared__ uint32_t Bs_l[2][8][32][2];
    __shared__ int rows[128];

    const int tid  = threadIdx.x;
    const int m0   = blockIdx.x * 128;
    const int n0   = blockIdx.y * 64;
    const int lane = tid & 31;
    const int warp = tid >> 5;
    const int wm   = warp & 3;   // 4 m-slices of 32 rows
    const int wn   = warp >> 2;  // 2 n-slices of 32 cols

    for (int i = tid; i < 128; i += 256) rows[i] = tokens[m0 + i];
    __syncthreads();

    // Loader assignment
    const int ar  = tid >> 1;           // A row 0..127
    const int ac4 = (tid & 1) * 4;      // A col group (0 or 4)
    const int bk  = tid >> 5;           // B k row 0..7
    const int bn2 = (tid & 31) * 2;     // B col 0..62

    const float* aptr = emb + (size_t)rows[ar] * E_ + ac4;
    const float* bptr = W + (size_t)bk * U_ + n0 + bn2;

    // Precompute A write targets
    const int a_mf   = ar >> 4;
    const int a_r16  = ar & 15;
    const int a_lnb  = (a_r16 & 7) << 2;
    const int a_slr  = (a_r16 >> 3) & 1;
    // B write targets per element j in {0,1}: n = bn2+j
    const int b_sl   = bk >> 2;
    const int b_kt   = bk & 3;

    float acc[2][4][4];
#pragma unroll
    for (int i = 0; i < 2; i++)
#pragma unroll
        for (int j = 0; j < 4; j++)
#pragma unroll
            for (int q = 0; q < 4; q++) acc[i][j][q] = 0.f;

    float4 av = *reinterpret_cast<const float4*>(aptr);
    float2 bv = *reinterpret_cast<const float2*>(bptr);

    // store tile into buf
    auto store_tile = [&](int buf, float4 a, float2 b) {
        float ae[4] = {a.x, a.y, a.z, a.w};
#pragma unroll
        for (int j = 0; j < 4; j++) {
            int c  = ac4 + j;
            int sl = a_slr | ((c >> 2) << 1);
            int ln = a_lnb + (c & 3);
            uint32_t hi, lo; split_tf32(ae[j], hi, lo);
            As_h[buf][a_mf][ln][sl] = hi;
            As_l[buf][a_mf][ln][sl] = lo;
        }
        float be[2] = {b.x, b.y};
#pragma unroll
        for (int j = 0; j < 2; j++) {
            int n  = bn2 + j;
            int nf = n >> 3, n8 = n & 7;
            int ln = (n8 << 2) + b_kt;
            uint32_t hi, lo; split_tf32(be[j], hi, lo);
            Bs_h[buf][nf][ln][b_sl] = hi;
            Bs_l[buf][nf][ln][b_sl] = lo;
        }
    };

    store_tile(0, av, bv);
    __syncthreads();

    const int NK = E_ / 8;  // 64
    for (int kt = 0; kt < NK; kt++) {
        int buf = kt & 1;
        float4 av2; float2 bv2;
        if (kt + 1 < NK) {
            av2 = *reinterpret_cast<const float4*>(aptr + (kt + 1) * 8);
            bv2 = *reinterpret_cast<const float2*>(bptr + (size_t)(kt + 1) * 8 * U_);
        }
        // fragment loads (wide) + mma
        uint4 ah[2], al[2]; uint2 bh[4], bl[4];
#pragma unroll
        for (int i = 0; i < 2; i++) {
            ah[i] = *reinterpret_cast<uint4*>(As_h[buf][wm * 2 + i][lane]);
            al[i] = *reinterpret_cast<uint4*>(As_l[buf][wm * 2 + i][lane]);
        }
#pragma unroll
        for (int j = 0; j < 4; j++) {
            bh[j] = *reinterpret_cast<uint2*>(Bs_h[buf][wn * 4 + j][lane]);
            bl[j] = *reinterpret_cast<uint2*>(Bs_l[buf][wn * 4 + j][lane]);
        }
#pragma unroll
        for (int i = 0; i < 2; i++)
#pragma unroll
            for (int j = 0; j < 4; j++)
                mma3x(acc[i][j], (const uint32_t*)&ah[i], (const uint32_t*)&al[i],
                      (const uint32_t*)&bh[j], (const uint32_t*)&bl[j]);

        if (kt + 1 < NK) store_tile(buf ^ 1, av2, bv2);
        __syncthreads();
    }

    // Epilogue: + bias, store fp32
    const int g = lane >> 2, tg = lane & 3;
#pragma unroll
    for (int i = 0; i < 2; i++) {
        int row = m0 + (wm * 2 + i) * 16 + g;
#pragma unroll
        for (int j = 0; j < 4; j++) {
            int col = n0 + (wn * 4 + j) * 8 + tg * 2;
            float b0 = bias[col], b1 = bias[col + 1];
            float2 o0 = {acc[i][j][0] + b0, acc[i][j][1] + b1};
            float2 o1 = {acc[i][j][2] + b0, acc[i][j][3] + b1};
            *reinterpret_cast<float2*>(g_xk + (size_t)row * U_ + col) = o0;
            *reinterpret_cast<float2*>(g_xk + (size_t)(row + 8) * U_ + col) = o1;
        }
    }
}

// ---------------------------------------------------------------------------
// First step: h0 = 0  ->  h1 = tanh(xk[:, 0, :])
// ---------------------------------------------------------------------------
__global__ void first_step_kernel()
{
    int i = blockIdx.x * blockDim.x + threadIdx.x;
    if (i < B_ * U_) {
        int b = i / U_, u = i - b * U_;
        g_h[1][i] = tanhf(g_xk[((size_t)b * T_) * U_ + u]);
    }
}

// ---------------------------------------------------------------------------
// RNN step t (3xTF32 mma): g_h[cur^1] = tanh(xk[:,t,:] + g_h[cur] @ R)
// CTA tile 64x64, BK=16, 256 thr (8 warps, warp tile 16x32), double-buffered.
// Grid = (16, 8) = 128 CTAs.
// ---------------------------------------------------------------------------
__global__ void __launch_bounds__(256)
rnn_step_mma(const float* __restrict__ R, int t, int cur)
{
    __shared__ uint32_t As_h[2][2][4][32][4];  // [buf][k8][mfrag][lane][slot]
    __shared__ uint32_t As_l[2][2][4][32][4];
    __shared__ uint32_t Bs_h[2][2][8][32][2];  // [buf][k8][nfrag][lane][slot]
    __shared__ uint32_t Bs_l[2][2][8][32][2];

    const int tid  = threadIdx.x;
    const int m0   = blockIdx.x * 64;
    const int n0   = blockIdx.y * 64;
    const int lane = tid & 31;
    const int warp = tid >> 5;
    const int wm   = warp & 3;   // mfrag index (16 rows)
    const int wn   = warp >> 2;  // 2 n-slices of 32 cols

    const float* __restrict__ H  = g_h[cur];
    float* __restrict__ Hn       = g_h[cur ^ 1];

    // Loader assignment: A: 64x16; B: 16x64
    const int ar  = tid >> 2;          // 0..63
    const int ac4 = (tid & 3) * 4;     // 0..12
    const int bk  = tid >> 4;          // 0..15
    const int bn4 = (tid & 15) * 4;    // 0..60

    const float* aptr = H + (size_t)(m0 + ar) * U_ + ac4;
    const float* bptr = R + (size_t)bk * U_ + n0 + bn4;

    const int a_mf  = ar >> 4;
    const int a_r16 = ar & 15;
    const int a_lnb = (a_r16 & 7) << 2;
    const int a_slr = (a_r16 >> 3) & 1;
    const int b_k8i = bk >> 3;
    const int b_k8r = bk & 7;
    const int b_sl  = b_k8r >> 2;
    const int b_kt  = b_k8r & 3;

    float acc[4][4];
#pragma unroll
    for (int j = 0; j < 4; j++)
#pragma unroll
        for (int q = 0; q < 4; q++) acc[j][q] = 0.f;

    float4 av = *reinterpret_cast<const float4*>(aptr);
    float4 bv = *reinterpret_cast<const float4*>(bptr);

    auto store_tile = [&](int buf, float4 a, float4 b) {
        float ae[4] = {a.x, a.y, a.z, a.w};
#pragma unroll
        for (int j = 0; j < 4; j++) {
            int c   = ac4 + j;           // 0..15
            int k8i = c >> 3;
            int c8  = c & 7;
            int sl  = a_slr | ((c8 >> 2) << 1);
            int ln  = a_lnb + (c8 & 3);
            uint32_t hi, lo; split_tf32(ae[j], hi, lo);
            As_h[buf][k8i][a_mf][ln][sl] = hi;
            As_l[buf][k8i][a_mf][ln][sl] = lo;
        }
        float be[4] = {b.x, b.y, b.z, b.w};
#pragma unroll
        for (int j = 0; j < 4; j++) {
            int n  = bn4 + j;
            int nf = n >> 3, n8 = n & 7;
            int ln = (n8 << 2) + b_kt;
            uint32_t hi, lo; split_tf32(be[j], hi, lo);
            Bs_h[buf][b_k8i][nf][ln][b_sl] = hi;
            Bs_l[buf][b_k8i][nf][ln][b_sl] = lo;
        }
    };

    store_tile(0, av, bv);
    __syncthreads();

    const int NK = U_ / 16;  // 32
    for (int kt = 0; kt < NK; kt++) {
        int buf = kt & 1;
        float4 av2, bv2;
        if (kt + 1 < NK) {
            av2 = *reinterpret_cast<const float4*>(aptr + (kt + 1) * 16);
            bv2 = *reinterpret_cast<const float4*>(bptr + (size_t)(kt + 1) * 16 * U_);
        }
#pragma unroll
        for (int k8 = 0; k8 < 2; k8++) {
            uint4 ah = *reinterpret_cast<uint4*>(As_h[buf][k8][wm][lane]);
            uint4 al = *reinterpret_cast<uint4*>(As_l[buf][k8][wm][lane]);
            uint2 bh[4], bl[4];
#pragma unroll
            for (int j = 0; j < 4; j++) {
                bh[j] = *reinterpret_cast<uint2*>(Bs_h[buf][k8][wn * 4 + j][lane]);
                bl[j] = *reinterpret_cast<uint2*>(Bs_l[buf][k8][wn * 4 + j][lane]);
            }
#pragma unroll
            for (int j = 0; j < 4; j++)
                mma3x(acc[j], (const uint32_t*)&ah, (const uint32_t*)&al,
                      (const uint32_t*)&bh[j], (const uint32_t*)&bl[j]);
        }
        if (kt + 1 < NK) store_tile(buf ^ 1, av2, bv2);
        __syncthreads();
    }

    // Epilogue: + xk[:, t, :], tanh, store next h
    const int g = lane >> 2, tg = lane & 3;
    const int row = m0 + wm * 16 + g;  // batch index
#pragma unroll
    for (int j = 0; j < 4; j++) {
        int col = n0 + wn * 32 + j * 8 + tg * 2;
        {
            float2 xv = *reinterpret_cast<const float2*>(
                g_xk + ((size_t)row * T_ + t) * U_ + col);
            float2 o = {tanhf(acc[j][0] + xv.x), tanhf(acc[j][1] + xv.y)};
            *reinterpret_cast<float2*>(Hn + (size_t)row * U_ + col) = o;
        }
        {
            float2 xv = *reinterpret_cast<const float2*>(
                g_xk + ((size_t)(row + 8) * T_ + t) * U_ + col);
            float2 o = {tanhf(acc[j][2] + xv.x), tanhf(acc[j][3] + xv.y)};
            *reinterpret_cast<float2*>(Hn + (size_t)(row + 8) * U_ + col) = o;
        }
    }
}

// ---------------------------------------------------------------------------
// Final: out[b] = sigmoid(h[b] . fc_w + fc_b)   (one warp per row)
// ---------------------------------------------------------------------------
__global__ void final_kernel(const float* __restrict__ fc_w,
                             const float* __restrict__ fc_b,
                             float* __restrict__ out,
                             int hbuf)
{
    int gw = (blockIdx.x * blockDim.x + threadIdx.x) >> 5;
    int lane = threadIdx.x & 31;
    if (gw >= B_) return;
    const float* h = g_h[hbuf] + (size_t)gw * U_;
    float s = 0.f;
    for (int i = lane; i < U_; i += 32) s = fmaf(h[i], fc_w[i], s);
#pragma unroll
    for (int o = 16; o; o >>= 1) s += __shfl_xor_sync(0xffffffffu, s, o);
    if (lane == 0) out[gw] = 1.f / (1.f + expf(-(s + fc_b[0])));
}

// ---------------------------------------------------------------------------
// Launch
// ---------------------------------------------------------------------------
extern "C" void kernel_launch(void* const* d_in, const int* in_sizes, int n_in,
                              void* d_out, int out_size)
{
    const int*   tokens     = (const int*)  d_in[0];   // [B, T]
    const float* emb        = (const float*)d_in[1];   // [V, E]
    const float* kernel     = (const float*)d_in[2];   // [E, U]
    const float* rec_kernel = (const float*)d_in[3];   // [U, U]
    const float* bias       = (const float*)d_in[4];   // [U]
    const float* fc_w       = (const float*)d_in[5];   // [U, 1]
    const float* fc_b       = (const float*)d_in[6];   // [1]
    float* out = (float*)d_out;                        // [B, 1]

    // 1) Input projection for all timesteps (3xTF32 tensor GEMM, gather fused)
    dim3 g1(M1 / 128, U_ / 64);   // (640, 8)
    gemm_embed_mma<<<g1, 256>>>(tokens, emb, kernel, bias);

    // 2) t = 0: h = tanh(xk_0)   (h0 == 0, GEMM skipped)
    first_step_kernel<<<(B_ * U_ + 255) / 256, 256>>>();

    // 3) t = 1..79: sequential recurrence (ping-pong buffers)
    dim3 g2(B_ / 64, U_ / 64);    // (16, 8) = 128 CTAs
    int cur = 1;
    for (int t = 1; t < T_; t++) {
        rnn_step_mma<<<g2, 256>>>(rec_kernel, t, cur);
        cur ^= 1;
    }
    // After 79 flips starting at 1 -> final h lives in g_h[0]

    // 4) Classifier head + sigmoid
    final_kernel<<<B_ / 8, 256>>>(fc_w, fc_b, out, cur);
}

// round 7
// speedup vs baseline: 1.1209x; 1.1209x over previous
#include <cuda_runtime.h>
#include <math.h>
#include <stdint.h>

// Problem constants (fixed by the reference)
#define B_  1024
#define T_  80
#define E_  512
#define U_  512
#define M1  (B_ * T_)   // 81920 rows of the input-projection GEMM

// Static device scratch (allocation-free rule: __device__ globals)
__device__ float g_xk[(size_t)M1 * U_];   // [B*T, U] input projection (+bias)

// R in B-fragment order, tf32-split, packed {bh0,bh1,bl0,bl1} per lane.
// Index [kb][nf][lane], kb,nf in [0,64).
__device__ uint4 g_Bfrag[64 * 64 * 32];

// h in A-fragment order, tf32-split: per lane 8 u32 = hi[4 slots] | lo[4 slots].
// Index ((mf*64 + kb)*32 + lane)*8 + (hi? slot : 4+slot). Ping-pong.
__device__ uint32_t g_Afrag[2][(size_t)64 * 64 * 32 * 8];

// ---------------------------------------------------------------------------
// Helpers
// ---------------------------------------------------------------------------
__device__ __forceinline__ void split_tf32(float x, uint32_t& hi, uint32_t& lo)
{
    asm("cvt.rna.tf32.f32 %0, %1;" : "=r"(hi) : "f"(x));
    float r = x - __uint_as_float(hi);
    asm("cvt.rna.tf32.f32 %0, %1;" : "=r"(lo) : "f"(r));
}

__device__ __forceinline__ void mma8(float* c, const uint32_t* a, const uint32_t* b)
{
    asm volatile(
        "mma.sync.aligned.m16n8k8.row.col.f32.tf32.tf32.f32 "
        "{%0,%1,%2,%3}, {%4,%5,%6,%7}, {%8,%9}, {%0,%1,%2,%3};"
        : "+f"(c[0]), "+f"(c[1]), "+f"(c[2]), "+f"(c[3])
        : "r"(a[0]), "r"(a[1]), "r"(a[2]), "r"(a[3]), "r"(b[0]), "r"(b[1]));
}

// 3xTF32: d += hi*lo' + lo*hi' + hi*hi'  (drops lo*lo; ~fp32 accuracy)
__device__ __forceinline__ void mma3x(float* c,
                                      const uint32_t* ah, const uint32_t* al,
                                      const uint32_t* bh, const uint32_t* bl)
{
    mma8(c, ah, bl);
    mma8(c, al, bh);
    mma8(c, ah, bh);
}

__device__ __forceinline__ void cp16(uint32_t saddr, const void* gptr)
{
    asm volatile("cp.async.cg.shared.global [%0], [%1], 16;\n"
                 :: "r"(saddr), "l"(gptr) : "memory");
}
__device__ __forceinline__ uint32_t saddr_of(const void* p)
{
    return (uint32_t)__cvta_generic_to_shared(p);
}

// Fragment maps (m16n8k8, row.col):
//  A (r16, c8): lane = (r16&7)*4 + (c8&3), slot = ((r16>>3)&1) | ((c8>>2)<<1)
//  B (k8, n8):  lane = n8*4 + (k8&3),      slot = k8>>2
//  C (r16, n8): lane = (r16&7)*4 + (n8>>1); c0,c1 = row g cols 2tg,2tg+1; c2,c3 = row g+8

// ---------------------------------------------------------------------------
// prep_R: R [512x512] fp32 -> g_Bfrag (hi/lo packed uint4 per lane)
// ---------------------------------------------------------------------------
__global__ void prep_R_kernel(const float* __restrict__ R)
{
    int id = blockIdx.x * 256 + threadIdx.x;      // < 64*64*32 = 131072
    int lane = id & 31, nf = (id >> 5) & 63, kb = id >> 11;
    int tg = lane & 3, n = lane >> 2;
    float e0 = R[(size_t)(kb * 8 + tg) * U_ + nf * 8 + n];        // k = tg   (slot 0)
    float e1 = R[(size_t)(kb * 8 + tg + 4) * U_ + nf * 8 + n];    // k = tg+4 (slot 1)
    uint32_t h0, l0, h1, l1;
    split_tf32(e0, h0, l0);
    split_tf32(e1, h1, l1);
    g_Bfrag[id] = make_uint4(h0, h1, l0, l1);
}

// ---------------------------------------------------------------------------
// Kernel 1 (3xTF32 mma): g_xk[m,n] = sum_e emb[tokens[m],e]*W[e,n] + bias[n]
// (unchanged from R6 — known good)
// ---------------------------------------------------------------------------
__global__ void __launch_bounds__(256)
gemm_embed_mma(const int* __restrict__ tokens,
               const float* __restrict__ emb,
               const float* __restrict__ W,
               const float* __restrict__ bias)
{
    __shared__ uint32_t As_h[2][8][32][4];
    __shared__ uint32_t As_l[2][8][32][4];
    __shared__ uint32_t Bs_h[2][8][32][2];
    __shared__ uint32_t Bs_l[2][8][32][2];
    __shared__ int rows[128];

    const int tid  = threadIdx.x;
    const int m0   = blockIdx.x * 128;
    const int n0   = blockIdx.y * 64;
    const int lane = tid & 31;
    const int warp = tid >> 5;
    const int wm   = warp & 3;
    const int wn   = warp >> 2;

    for (int i = tid; i < 128; i += 256) rows[i] = tokens[m0 + i];
    __syncthreads();

    const int ar  = tid >> 1;
    const int ac4 = (tid & 1) * 4;
    const int bk  = tid >> 5;
    const int bn2 = (tid & 31) * 2;

    const float* aptr = emb + (size_t)rows[ar] * E_ + ac4;
    const float* bptr = W + (size_t)bk * U_ + n0 + bn2;

    const int a_mf   = ar >> 4;
    const int a_r16  = ar & 15;
    const int a_lnb  = (a_r16 & 7) << 2;
    const int a_slr  = (a_r16 >> 3) & 1;
    const int b_sl   = bk >> 2;
    const int b_kt   = bk & 3;

    float acc[2][4][4];
#pragma unroll
    for (int i = 0; i < 2; i++)
#pragma unroll
        for (int j = 0; j < 4; j++)
#pragma unroll
            for (int q = 0; q < 4; q++) acc[i][j][q] = 0.f;

    float4 av = *reinterpret_cast<const float4*>(aptr);
    float2 bv = *reinterpret_cast<const float2*>(bptr);

    auto store_tile = [&](int buf, float4 a, float2 b) {
        float ae[4] = {a.x, a.y, a.z, a.w};
#pragma unroll
        for (int j = 0; j < 4; j++) {
            int c  = ac4 + j;
            int sl = a_slr | ((c >> 2) << 1);
            int ln = a_lnb + (c & 3);
            uint32_t hi, lo; split_tf32(ae[j], hi, lo);
            As_h[buf][a_mf][ln][sl] = hi;
            As_l[buf][a_mf][ln][sl] = lo;
        }
        float be[2] = {b.x, b.y};
#pragma unroll
        for (int j = 0; j < 2; j++) {
            int n  = bn2 + j;
            int nf = n >> 3, n8 = n & 7;
            int ln = (n8 << 2) + b_kt;
            uint32_t hi, lo; split_tf32(be[j], hi, lo);
            Bs_h[buf][nf][ln][b_sl] = hi;
            Bs_l[buf][nf][ln][b_sl] = lo;
        }
    };

    store_tile(0, av, bv);
    __syncthreads();

    const int NK = E_ / 8;
    for (int kt = 0; kt < NK; kt++) {
        int buf = kt & 1;
        float4 av2; float2 bv2;
        if (kt + 1 < NK) {
            av2 = *reinterpret_cast<const float4*>(aptr + (kt + 1) * 8);
            bv2 = *reinterpret_cast<const float2*>(bptr + (size_t)(kt + 1) * 8 * U_);
        }
        uint4 ah[2], al[2]; uint2 bh[4], bl[4];
#pragma unroll
        for (int i = 0; i < 2; i++) {
            ah[i] = *reinterpret_cast<uint4*>(As_h[buf][wm * 2 + i][lane]);
            al[i] = *reinterpret_cast<uint4*>(As_l[buf][wm * 2 + i][lane]);
        }
#pragma unroll
        for (int j = 0; j < 4; j++) {
            bh[j] = *reinterpret_cast<uint2*>(Bs_h[buf][wn * 4 + j][lane]);
            bl[j] = *reinterpret_cast<uint2*>(Bs_l[buf][wn * 4 + j][lane]);
        }
#pragma unroll
        for (int i = 0; i < 2; i++)
#pragma unroll
            for (int j = 0; j < 4; j++)
                mma3x(acc[i][j], (const uint32_t*)&ah[i], (const uint32_t*)&al[i],
                      (const uint32_t*)&bh[j], (const uint32_t*)&bl[j]);

        if (kt + 1 < NK) store_tile(buf ^ 1, av2, bv2);
        __syncthreads();
    }

    const int g = lane >> 2, tg = lane & 3;
#pragma unroll
    for (int i = 0; i < 2; i++) {
        int row = m0 + (wm * 2 + i) * 16 + g;
#pragma unroll
        for (int j = 0; j < 4; j++) {
            int col = n0 + (wn * 4 + j) * 8 + tg * 2;
            float b0 = bias[col], b1 = bias[col + 1];
            float2 o0 = {acc[i][j][0] + b0, acc[i][j][1] + b1};
            float2 o1 = {acc[i][j][2] + b0, acc[i][j][3] + b1};
            *reinterpret_cast<float2*>(g_xk + (size_t)row * U_ + col) = o0;
            *reinterpret_cast<float2*>(g_xk + (size_t)(row + 8) * U_ + col) = o1;
        }
    }
}

// ---------------------------------------------------------------------------
// First step: h1 = tanh(xk[:,0,:]) written split, A-fragment order, to pp=0
// ---------------------------------------------------------------------------
__global__ void first_step_frag()
{
    int id = blockIdx.x * 256 + threadIdx.x;     // < B_*U_
    int u = id & 511, b = id >> 9;
    float v = tanhf(g_xk[((size_t)b * T_) * U_ + u]);
    uint32_t hi, lo; split_tf32(v, hi, lo);
    int mf = b >> 4, r16 = b & 15, kb = u >> 3, c8 = u & 7;
    int lp = ((r16 & 7) << 2) | (c8 & 3);
    int sl = ((r16 >> 3) & 1) | ((c8 >> 2) << 1);
    size_t base = ((((size_t)mf * 64) + kb) * 32 + lp) * 8;
    g_Afrag[0][base + sl] = hi;
    g_Afrag[0][base + 4 + sl] = lo;
}

// ---------------------------------------------------------------------------
// RNN step t: h' = tanh(xk[:,t,:] + h @ R), everything pre-split/fragmented.
// CTA 64x64, 8 warps (warp tile 16x32), grid (16,8)=128.
// 3-stage cp.async pipeline, 2 k8-blocks per stage.
// ---------------------------------------------------------------------------
#define S_ 3
__global__ void __launch_bounds__(256)
rnn_step_frag(int t, int pp)
{
    __shared__ __align__(16) uint32_t sA[S_][4][2][32][8]; // [stage][mf][kbL][lane][hi4|lo4]
    __shared__ __align__(16) uint32_t sB[S_][8][2][32][4]; // [stage][nf][kbL][lane][bh2|bl2]

    const int tid  = threadIdx.x;
    const int lane = tid & 31;
    const int warp = tid >> 5;
    const int wm   = warp >> 1;   // mfrag (16 rows)
    const int wn   = warp & 1;    // 4-nfrag group (32 cols)
    const int bm   = blockIdx.x;  // 0..15
    const int bn   = blockIdx.y;  // 0..7
    const int m0f  = bm * 4;
    const int n0f  = bn * 8;

    const uint32_t* __restrict__ Ag   = g_Afrag[pp];
    uint32_t* __restrict__       Aout = g_Afrag[pp ^ 1];
    const uint4* __restrict__    Bg   = g_Bfrag;

    // copy-duty constants (4 x 16B per thread per stage)
    const int h_ = tid & 1;         // A hi/lo half
    const int a0 = tid >> 1;        // A sub-chunk id (0..127; +128)

    float acc[4][4];
#pragma unroll
    for (int j = 0; j < 4; j++)
#pragma unroll
        for (int q = 0; q < 4; q++) acc[j][q] = 0.f;

    auto issue = [&](int kt2) {
        if (kt2 < 32) {
            const int s   = kt2 % S_;
            const int kb0 = kt2 << 1;
#pragma unroll
            for (int i = 0; i < 2; i++) {                 // A: 2 chunks
                int a   = a0 + (i << 7);
                int la  = a & 31;
                int kbL = (a >> 5) & 1;
                int mf  = a >> 6;
                const uint32_t* gp = Ag +
                    ((((size_t)(m0f + mf) * 64) + kb0 + kbL) * 32 + la) * 8 + (h_ << 2);
                cp16(saddr_of(&sA[s][mf][kbL][la][h_ << 2]), gp);
            }
#pragma unroll
            for (int i = 0; i < 2; i++) {                 // B: 2 chunks
                int r   = tid + (i << 8);
                int la  = r & 31;
                int kbL = (r >> 5) & 1;
                int nf  = r >> 6;
                const uint4* gp = Bg + (((size_t)(kb0 + kbL) * 64) + n0f + nf) * 32 + la;
                cp16(saddr_of(&sB[s][nf][kbL][la][0]), gp);
            }
        }
        asm volatile("cp.async.commit_group;\n" ::: "memory");
    };

    issue(0);
    issue(1);

    for (int kt = 0; kt < 32; kt++) {
        asm volatile("cp.async.wait_group 1;\n" ::: "memory");
        __syncthreads();
        issue(kt + 2);            // fills slot (kt-1)%3, consumed last iter
        const int s = kt % S_;
#pragma unroll
        for (int j = 0; j < 2; j++) {
            uint4 ah = *reinterpret_cast<const uint4*>(&sA[s][wm][j][lane][0]);
            uint4 al = *reinterpret_cast<const uint4*>(&sA[s][wm][j][lane][4]);
#pragma unroll
            for (int nfi = 0; nfi < 4; nfi++) {
                uint4 bq = *reinterpret_cast<const uint4*>(&sB[s][wn * 4 + nfi][j][lane][0]);
                uint32_t bh[2] = {bq.x, bq.y};
                uint32_t bl[2] = {bq.z, bq.w};
                mma3x(acc[nfi], &ah.x, &al.x, bh, bl);
            }
        }
    }

    // Epilogue: + xk[:,t,:], tanh, write split A-fragments for next step
    const int g  = lane >> 2, tg = lane & 3;
    const int r0 = bm * 64 + wm * 16 + g;     // batch row
    const int mfg = r0 >> 4;                  // = bm*4 + wm
#pragma unroll
    for (int nfi = 0; nfi < 4; nfi++) {
        const int nf = n0f + wn * 4 + nfi;
        const int c  = nf * 8 + tg * 2;
        float2 x0 = *reinterpret_cast<const float2*>(g_xk + ((size_t)r0 * T_ + t) * U_ + c);
        float2 x1 = *reinterpret_cast<const float2*>(g_xk + ((size_t)(r0 + 8) * T_ + t) * U_ + c);
        float h00 = tanhf(acc[nfi][0] + x0.x);
        float h01 = tanhf(acc[nfi][1] + x0.y);
        float h10 = tanhf(acc[nfi][2] + x1.x);
        float h11 = tanhf(acc[nfi][3] + x1.y);

        size_t base = (((size_t)mfg * 64) + nf) * 32 * 8;
        int c80 = 2 * tg, c81 = 2 * tg + 1;
        int lp0 = (g << 2) | (c80 & 3);
        int lp1 = (g << 2) | (c81 & 3);
        int s00 = ((c80 >> 2) << 1);        // row g
        int s01 = ((c81 >> 2) << 1);
        int s10 = 1 | s00;                  // row g+8
        int s11 = 1 | s01;

        uint32_t hi, lo;
        split_tf32(h00, hi, lo);
        Aout[base + lp0 * 8 + s00] = hi; Aout[base + lp0 * 8 + 4 + s00] = lo;
        split_tf32(h01, hi, lo);
        Aout[base + lp1 * 8 + s01] = hi; Aout[base + lp1 * 8 + 4 + s01] = lo;
        split_tf32(h10, hi, lo);
        Aout[base + lp0 * 8 + s10] = hi; Aout[base + lp0 * 8 + 4 + s10] = lo;
        split_tf32(h11, hi, lo);
        Aout[base + lp1 * 8 + s11] = hi; Aout[base + lp1 * 8 + 4 + s11] = lo;
    }
}

// ---------------------------------------------------------------------------
// Final: out[b] = sigmoid(h[b] . fc_w + fc_b), h read from fragment layout
// ---------------------------------------------------------------------------
__global__ void final_frag(const float* __restrict__ fc_w,
                           const float* __restrict__ fc_b,
                           float* __restrict__ out)
{
    int gw = (blockIdx.x * blockDim.x + threadIdx.x) >> 5;   // batch row
    int lane = threadIdx.x & 31;
    if (gw >= B_) return;
    const uint32_t* A = g_Afrag[1];
    int mf = gw >> 4, r16 = gw & 15;
    int lb = (r16 & 7) << 2, srb = (r16 >> 3) & 1;
    float s = 0.f;
    for (int u = lane; u < U_; u += 32) {
        int kb = u >> 3, c8 = u & 7;
        size_t idx = ((((size_t)mf * 64) + kb) * 32 + (lb | (c8 & 3))) * 8
                     + (srb | ((c8 >> 2) << 1));
        float v = __uint_as_float(A[idx]) + __uint_as_float(A[idx + 4]);
        s = fmaf(v, fc_w[u], s);
    }
#pragma unroll
    for (int o = 16; o; o >>= 1) s += __shfl_xor_sync(0xffffffffu, s, o);
    if (lane == 0) out[gw] = 1.f / (1.f + expf(-(s + fc_b[0])));
}

// ---------------------------------------------------------------------------
// Launch
// ---------------------------------------------------------------------------
extern "C" void kernel_launch(void* const* d_in, const int* in_sizes, int n_in,
                              void* d_out, int out_size)
{
    const int*   tokens     = (const int*)  d_in[0];   // [B, T]
    const float* emb        = (const float*)d_in[1];   // [V, E]
    const float* kernel     = (const float*)d_in[2];   // [E, U]
    const float* rec_kernel = (const float*)d_in[3];   // [U, U]
    const float* bias       = (const float*)d_in[4];   // [U]
    const float* fc_w       = (const float*)d_in[5];   // [U, 1]
    const float* fc_b       = (const float*)d_in[6];   // [1]
    float* out = (float*)d_out;                        // [B, 1]

    // 0) R -> fragment order, tf32-split (once)
    prep_R_kernel<<<512, 256>>>(rec_kernel);

    // 1) Input projection for all timesteps (3xTF32 tensor GEMM, gather fused)
    dim3 g1(M1 / 128, U_ / 64);   // (640, 8)
    gemm_embed_mma<<<g1, 256>>>(tokens, emb, kernel, bias);

    // 2) t = 0: h = tanh(xk_0) -> split fragments (pp = 0)
    first_step_frag<<<(B_ * U_) / 256, 256>>>();

    // 3) t = 1..79: recurrence; reads g_Afrag[(t-1)&1], writes g_Afrag[t&1]
    dim3 g2(B_ / 64, U_ / 64);    // (16, 8) = 128 CTAs
    for (int t = 1; t < T_; t++)
        rnn_step_frag<<<g2, 256>>>(t, (t - 1) & 1);
    // t = 79 writes g_Afrag[1]

    // 4) Classifier head + sigmoid
    final_frag<<<B_ / 8, 256>>>(fc_w, fc_b, out);
}

// round 8
// speedup vs baseline: 3.2452x; 2.8951x over previous
#include <cuda_runtime.h>
#include <cuda_bf16.h>
#include <math.h>
#include <stdint.h>

// Problem constants (fixed by the reference)
#define B_  1024
#define T_  80
#define E_  512
#define U_  512
#define M1  (B_ * T_)

// Static device scratch (allocation-free rule: __device__ globals)
__device__ float g_xk[(size_t)M1 * U_];   // [B*T, U] input projection (+bias)

// 512x512 weight matrices in B-fragment order (m16n8k16 bf16), hi/lo split:
// uint4 {bh0, bh1, bl0, bl1} per [kb16 (32)][nf (64)][lane (32)].
//  b0: k = kb16*16 + 2*(lane&3) + {0,1}, n = nf*8 + (lane>>2);  b1: k += 8.
__device__ uint4 g_Bfrag[32 * 64 * 32];   // rec_kernel R
__device__ uint4 g_Wfrag[32 * 64 * 32];   // input kernel W

// h in A-fragment order (m16n8k16 bf16), hi/lo split. Per lane 8 u32:
// regs 0..3 = hi {a0,a1,a2,a3}, regs 4..7 = lo. Ping-pong.
// A element (r16, k16): lane = (r16&7)*4 + ((k&7)>>1),
//   reg = (r16>>3) | ((k>>3)<<1), half = k&1 (low half = even k).
// Index: ((mf*32 + kb16)*32 + lane)*8 + reg.
__device__ uint32_t g_Afrag[2][(size_t)64 * 32 * 32 * 8];

// ---------------------------------------------------------------------------
// Helpers
// ---------------------------------------------------------------------------
__device__ __forceinline__ void split2(float a, float b, uint32_t& hp, uint32_t& lp)
{
    __nv_bfloat16 ah = __float2bfloat16_rn(a);
    __nv_bfloat16 bh = __float2bfloat16_rn(b);
    float ar = a - __bfloat162float(ah);
    float br = b - __bfloat162float(bh);
    __nv_bfloat16 al = __float2bfloat16_rn(ar);
    __nv_bfloat16 bl = __float2bfloat16_rn(br);
    hp = (uint32_t)__bfloat16_as_ushort(ah) | ((uint32_t)__bfloat16_as_ushort(bh) << 16);
    lp = (uint32_t)__bfloat16_as_ushort(al) | ((uint32_t)__bfloat16_as_ushort(bl) << 16);
}

__device__ __forceinline__ void mma16(float* c, const uint32_t* a, const uint32_t* b)
{
    asm volatile(
        "mma.sync.aligned.m16n8k16.row.col.f32.bf16.bf16.f32 "
        "{%0,%1,%2,%3}, {%4,%5,%6,%7}, {%8,%9}, {%0,%1,%2,%3};"
        : "+f"(c[0]), "+f"(c[1]), "+f"(c[2]), "+f"(c[3])
        : "r"(a[0]), "r"(a[1]), "r"(a[2]), "r"(a[3]), "r"(b[0]), "r"(b[1]));
}

// bf16x3: d += hi*lo' + lo*hi' + hi*hi'  (drops lo*lo; ~16-bit mantissa accuracy)
__device__ __forceinline__ void mma3x(float* c,
                                      const uint32_t* ah, const uint32_t* al,
                                      const uint32_t* bh, const uint32_t* bl)
{
    mma16(c, ah, bl);
    mma16(c, al, bh);
    mma16(c, ah, bh);
}

__device__ __forceinline__ void cp16(uint32_t saddr, const void* gptr)
{
    asm volatile("cp.async.cg.shared.global [%0], [%1], 16;\n"
                 :: "r"(saddr), "l"(gptr) : "memory");
}
__device__ __forceinline__ uint32_t saddr_of(const void* p)
{
    return (uint32_t)__cvta_generic_to_shared(p);
}

// ---------------------------------------------------------------------------
// prep: 512x512 row-major fp32 -> B-fragment order, bf16 hi/lo split
// ---------------------------------------------------------------------------
__global__ void prep_frag_512(const float* __restrict__ M, uint4* __restrict__ dst)
{
    int id = blockIdx.x * 256 + threadIdx.x;      // < 32*64*32 = 65536
    int lane = id & 31, nf = (id >> 5) & 63, kb = id >> 11;
    int tg = lane & 3, n = nf * 8 + (lane >> 2);
    int k0 = kb * 16 + 2 * tg;
    float e00 = M[(size_t)k0 * 512 + n];
    float e01 = M[(size_t)(k0 + 1) * 512 + n];
    float e10 = M[(size_t)(k0 + 8) * 512 + n];
    float e11 = M[(size_t)(k0 + 9) * 512 + n];
    uint32_t bh0, bl0, bh1, bl1;
    split2(e00, e01, bh0, bl0);
    split2(e10, e11, bh1, bl1);
    dst[id] = make_uint4(bh0, bh1, bl0, bl1);
}

// ---------------------------------------------------------------------------
// Embed GEMM (bf16x3): g_xk[m,n] = sum_e emb[tokens[m],e]*W[e,n] + bias[n]
// CTA 128x64, 8 warps (warp 32x32), K-tile 16, double-buffered.
// W comes pre-split from g_Wfrag via cp.async; A split in-kernel.
// ---------------------------------------------------------------------------
__global__ void __launch_bounds__(256)
gemm_embed_bf16(const int* __restrict__ tokens,
                const float* __restrict__ emb,
                const float* __restrict__ bias)
{
    __shared__ __align__(16) uint32_t sA[2][8][32][12]; // [buf][mf][lane][hi4|lo4|pad4]
    __shared__ __align__(16) uint4    sB[2][8][32];     // [buf][nf][lane]
    __shared__ int rows[128];

    const int tid  = threadIdx.x;
    const int m0   = blockIdx.x * 128;
    const int by   = blockIdx.y;            // 8 nf per CTA
    const int lane = tid & 31;
    const int warp = tid >> 5;
    const int wm   = warp & 3;              // 2 mf each
    const int wn   = warp >> 2;             // 4 nf each

    for (int i = tid; i < 128; i += 256) rows[i] = tokens[m0 + i];
    __syncthreads();

    // A loader: 2 threads per row, 8 consecutive k each
    const int ar  = tid >> 1;               // 0..127
    const int kh  = (tid & 1) * 8;          // 0 or 8
    const float* aptr = emb + (size_t)rows[ar] * E_ + kh;
    const int r16    = ar & 15;
    const int a_mf   = ar >> 4;
    const int a_lnb  = (r16 & 7) << 2;
    const int a_reg  = (r16 >> 3) | ((kh >> 3) << 1);

    // B loader: 1 cp16 per thread per k-tile
    const int b_nf   = tid >> 5;
    const int b_ln   = tid & 31;

    float acc[2][4][4];
#pragma unroll
    for (int i = 0; i < 2; i++)
#pragma unroll
        for (int j = 0; j < 4; j++)
#pragma unroll
            for (int q = 0; q < 4; q++) acc[i][j][q] = 0.f;

    auto cpB = [&](int kt, int buf) {
        const uint4* gp = g_Wfrag + (((size_t)kt * 64) + by * 8 + b_nf) * 32 + b_ln;
        cp16(saddr_of(&sB[buf][b_nf][b_ln]), gp);
    };
    auto storeA = [&](int buf, float4 a0, float4 a1) {
        float v[8] = {a0.x, a0.y, a0.z, a0.w, a1.x, a1.y, a1.z, a1.w};
#pragma unroll
        for (int p = 0; p < 4; p++) {
            uint32_t hp, lp;
            split2(v[2 * p], v[2 * p + 1], hp, lp);
            sA[buf][a_mf][a_lnb + p][a_reg]     = hp;
            sA[buf][a_mf][a_lnb + p][a_reg + 4] = lp;
        }
    };

    // Prologue
    float4 a0 = *reinterpret_cast<const float4*>(aptr);
    float4 a1 = *reinterpret_cast<const float4*>(aptr + 4);
    cpB(0, 0);
    asm volatile("cp.async.commit_group;\n" ::: "memory");
    storeA(0, a0, a1);
    asm volatile("cp.async.wait_group 0;\n" ::: "memory");
    __syncthreads();

    for (int kt = 0; kt < 32; kt++) {
        int buf = kt & 1;
        float4 a0n, a1n;
        if (kt + 1 < 32) {
            a0n = *reinterpret_cast<const float4*>(aptr + (kt + 1) * 16);
            a1n = *reinterpret_cast<const float4*>(aptr + (kt + 1) * 16 + 4);
            cpB(kt + 1, buf ^ 1);
        }
        asm volatile("cp.async.commit_group;\n" ::: "memory");

        uint4 ah[2], al[2];
#pragma unroll
        for (int i = 0; i < 2; i++) {
            ah[i] = *reinterpret_cast<const uint4*>(&sA[buf][wm * 2 + i][lane][0]);
            al[i] = *reinterpret_cast<const uint4*>(&sA[buf][wm * 2 + i][lane][4]);
        }
#pragma unroll
        for (int j = 0; j < 4; j++) {
            uint4 bq = sB[buf][wn * 4 + j][lane];
#pragma unroll
            for (int i = 0; i < 2; i++)
                mma3x(acc[i][j], &ah[i].x, &al[i].x, &bq.x, &bq.z);
        }

        if (kt + 1 < 32) storeA(buf ^ 1, a0n, a1n);
        asm volatile("cp.async.wait_group 0;\n" ::: "memory");
        __syncthreads();
    }

    // Epilogue: + bias, store fp32
    const int g = lane >> 2, tg = lane & 3;
#pragma unroll
    for (int i = 0; i < 2; i++) {
        int row = m0 + (wm * 2 + i) * 16 + g;
#pragma unroll
        for (int j = 0; j < 4; j++) {
            int col = by * 64 + (wn * 4 + j) * 8 + tg * 2;
            float b0 = bias[col], b1 = bias[col + 1];
            float2 o0 = {acc[i][j][0] + b0, acc[i][j][1] + b1};
            float2 o1 = {acc[i][j][2] + b0, acc[i][j][3] + b1};
            *reinterpret_cast<float2*>(g_xk + (size_t)row * U_ + col) = o0;
            *reinterpret_cast<float2*>(g_xk + (size_t)(row + 8) * U_ + col) = o1;
        }
    }
}

// ---------------------------------------------------------------------------
// First step: h1 = tanh(xk[:,0,:]) -> split A-fragments, pp=0
// ---------------------------------------------------------------------------
__global__ void first_step_frag()
{
    int id = blockIdx.x * 256 + threadIdx.x;    // < B_*256
    int b = id >> 8;
    int u0 = (id & 255) * 2;
    float v0 = tanhf(g_xk[((size_t)b * T_) * U_ + u0]);
    float v1 = tanhf(g_xk[((size_t)b * T_) * U_ + u0 + 1]);
    int mf = b >> 4, r16 = b & 15, kb = u0 >> 4, k = u0 & 15;
    int lane = ((r16 & 7) << 2) | ((k & 7) >> 1);
    int reg  = (r16 >> 3) | ((k >> 3) << 1);
    size_t base = ((((size_t)mf * 32) + kb) * 32 + lane) * 8;
    uint32_t hp, lp;
    split2(v0, v1, hp, lp);
    g_Afrag[0][base + reg]     = hp;
    g_Afrag[0][base + reg + 4] = lp;
}

// ---------------------------------------------------------------------------
// RNN step t: h' = tanh(xk[:,t,:] + h @ R)   (bf16x3, all pre-fragmented)
// CTA 64x64, 512 threads (16 warps, warp tile 16x16), grid (16,8).
// 3-stage cp.async pipeline, 2 k16-blocks per stage.
// ---------------------------------------------------------------------------
#define S_ 3
__global__ void __launch_bounds__(512)
rnn_step_frag(int t, int pp)
{
    __shared__ __align__(16) uint32_t sA[S_][4][2][32][12]; // [st][mf][kbL][lane][hi4|lo4|pad]
    __shared__ __align__(16) uint4    sB[S_][8][2][32];     // [st][nf][kbL][lane]

    const int tid  = threadIdx.x;
    const int lane = tid & 31;
    const int warp = tid >> 5;          // 0..15
    const int wm   = warp >> 2;         // mf 0..3
    const int wn   = warp & 3;          // 2 nf each
    const int bm   = blockIdx.x;        // 0..15
    const int bn   = blockIdx.y;        // 0..7
    const int m0f  = bm * 4;
    const int n0f  = bn * 8;

    const uint32_t* __restrict__ Ag   = g_Afrag[pp];
    uint32_t* __restrict__       Aout = g_Afrag[pp ^ 1];
    const uint4* __restrict__    Bg   = g_Bfrag;

    // Copy duty: 1 A-cp16 + 1 B-cp16 per thread per stage
    const int ca_ln  = tid & 31;
    const int ca_hl  = (tid >> 5) & 1;
    const int ca_kbL = (tid >> 6) & 1;
    const int ca_mf  = tid >> 7;
    const int cb_ln  = tid & 31;
    const int cb_kbL = (tid >> 5) & 1;
    const int cb_nf  = tid >> 6;

    float acc[2][4];
#pragma unroll
    for (int j = 0; j < 2; j++)
#pragma unroll
        for (int q = 0; q < 4; q++) acc[j][q] = 0.f;

    auto issue = [&](int kt2) {
        if (kt2 < 16) {
            const int s   = kt2 % S_;
            const int kb0 = kt2 << 1;
            const uint32_t* gpA = Ag +
                ((((size_t)(m0f + ca_mf) * 32) + kb0 + ca_kbL) * 32 + ca_ln) * 8 + (ca_hl << 2);
            cp16(saddr_of(&sA[s][ca_mf][ca_kbL][ca_ln][ca_hl << 2]), gpA);
            const uint4* gpB = Bg + (((size_t)(kb0 + cb_kbL) * 64) + n0f + cb_nf) * 32 + cb_ln;
            cp16(saddr_of(&sB[s][cb_nf][cb_kbL][cb_ln]), gpB);
        }
        asm volatile("cp.async.commit_group;\n" ::: "memory");
    };

    issue(0);
    issue(1);

    for (int kt = 0; kt < 16; kt++) {
        asm volatile("cp.async.wait_group 1;\n" ::: "memory");
        __syncthreads();
        issue(kt + 2);
        const int s = kt % S_;
#pragma unroll
        for (int kbL = 0; kbL < 2; kbL++) {
            uint4 ah = *reinterpret_cast<const uint4*>(&sA[s][wm][kbL][lane][0]);
            uint4 al = *reinterpret_cast<const uint4*>(&sA[s][wm][kbL][lane][4]);
#pragma unroll
            for (int nfi = 0; nfi < 2; nfi++) {
                uint4 bq = sB[s][wn * 2 + nfi][kbL][lane];
                mma3x(acc[nfi], &ah.x, &al.x, &bq.x, &bq.z);
            }
        }
    }

    // Epilogue: + xk[:,t,:], tanh, write split A-fragments for next step
    const int g  = lane >> 2, tg = lane & 3;
    const int r0 = bm * 64 + wm * 16 + g;
    const int mfg = bm * 4 + wm;
#pragma unroll
    for (int nfi = 0; nfi < 2; nfi++) {
        const int nf = n0f + wn * 2 + nfi;
        const int c  = nf * 8 + tg * 2;
        float2 x0 = *reinterpret_cast<const float2*>(g_xk + ((size_t)r0 * T_ + t) * U_ + c);
        float2 x1 = *reinterpret_cast<const float2*>(g_xk + ((size_t)(r0 + 8) * T_ + t) * U_ + c);
        float h00 = tanhf(acc[nfi][0] + x0.x);
        float h01 = tanhf(acc[nfi][1] + x0.y);
        float h10 = tanhf(acc[nfi][2] + x1.x);
        float h11 = tanhf(acc[nfi][3] + x1.y);

        uint32_t hp0, lp0, hp1, lp1;
        split2(h00, h01, hp0, lp0);
        split2(h10, h11, hp1, lp1);

        size_t base = ((((size_t)mfg * 32) + (nf >> 1)) * 32 + ((g << 2) | tg)) * 8;
        int rs = (nf & 1) << 1;
        Aout[base + rs]     = hp0;
        Aout[base + rs + 1] = hp1;
        Aout[base + rs + 4] = lp0;
        Aout[base + rs + 5] = lp1;
    }
}

// ---------------------------------------------------------------------------
// Final: out[b] = sigmoid(h[b] . fc_w + fc_b), h read from fragment layout
// ---------------------------------------------------------------------------
__global__ void final_frag(const float* __restrict__ fc_w,
                           const float* __restrict__ fc_b,
                           float* __restrict__ out)
{
    int gw = (blockIdx.x * blockDim.x + threadIdx.x) >> 5;
    int lane = threadIdx.x & 31;
    if (gw >= B_) return;
    const uint32_t* A = g_Afrag[1];
    int mf = gw >> 4, r16 = gw & 15;
    float s = 0.f;
    for (int u = lane; u < U_; u += 32) {
        int kb = u >> 4, k = u & 15;
        int li  = ((r16 & 7) << 2) | ((k & 7) >> 1);
        int reg = (r16 >> 3) | ((k >> 3) << 1);
        size_t base = ((((size_t)mf * 32) + kb) * 32 + li) * 8;
        uint32_t hw = A[base + reg], lw = A[base + reg + 4];
        uint16_t hb = (k & 1) ? (uint16_t)(hw >> 16) : (uint16_t)hw;
        uint16_t lb = (k & 1) ? (uint16_t)(lw >> 16) : (uint16_t)lw;
        float v = __bfloat162float(__ushort_as_bfloat16(hb))
                + __bfloat162float(__ushort_as_bfloat16(lb));
        s = fmaf(v, fc_w[u], s);
    }
#pragma unroll
    for (int o = 16; o; o >>= 1) s += __shfl_xor_sync(0xffffffffu, s, o);
    if (lane == 0) out[gw] = 1.f / (1.f + expf(-(s + fc_b[0])));
}

// ---------------------------------------------------------------------------
// Launch
// ---------------------------------------------------------------------------
extern "C" void kernel_launch(void* const* d_in, const int* in_sizes, int n_in,
                              void* d_out, int out_size)
{
    const int*   tokens     = (const int*)  d_in[0];   // [B, T]
    const float* emb        = (const float*)d_in[1];   // [V, E]
    const float* kernel     = (const float*)d_in[2];   // [E, U]
    const float* rec_kernel = (const float*)d_in[3];   // [U, U]
    const float* bias       = (const float*)d_in[4];   // [U]
    const float* fc_w       = (const float*)d_in[5];   // [U, 1]
    const float* fc_b       = (const float*)d_in[6];   // [1]
    float* out = (float*)d_out;                        // [B, 1]

    // 0) Pre-split weights into fragment order (once each)
    uint4* dB; cudaGetSymbolAddress((void**)&dB, g_Bfrag);
    uint4* dW; cudaGetSymbolAddress((void**)&dW, g_Wfrag);
    prep_frag_512<<<256, 256>>>(rec_kernel, dB);
    prep_frag_512<<<256, 256>>>(kernel, dW);

    // 1) Input projection for all timesteps (bf16x3 tensor GEMM, gather fused)
    dim3 g1(M1 / 128, U_ / 64);   // (640, 8)
    gemm_embed_bf16<<<g1, 256>>>(tokens, emb, bias);

    // 2) t = 0: h = tanh(xk_0) -> split fragments (pp = 0)
    first_step_frag<<<B_, 256>>>();

    // 3) t = 1..79: recurrence; reads g_Afrag[(t-1)&1], writes g_Afrag[t&1]
    dim3 g2(B_ / 64, U_ / 64);    // (16, 8) = 128 CTAs
    for (int t = 1; t < T_; t++)
        rnn_step_frag<<<g2, 512>>>(t, (t - 1) & 1);
    // t = 79 writes g_Afrag[1]

    // 4) Classifier head + sigmoid
    final_frag<<<B_ / 8, 256>>>(fc_w, fc_b, out);
}

// round 9
// speedup vs baseline: 3.4054x; 1.0494x over previous
#include <cuda_runtime.h>
#include <cuda_bf16.h>
#include <math.h>
#include <stdint.h>

// Problem constants (fixed by the reference)
#define B_  1024
#define T_  80
#define V_  50000
#define E_  512
#define U_  512

// Static device scratch (allocation-free rule: __device__ globals)
__device__ float g_proj[(size_t)V_ * U_];  // emb @ W + bias, per vocab row

// 512x512 weight matrices in B-fragment order (m16n8k16 bf16), hi/lo split:
// uint4 {bh0, bh1, bl0, bl1} per [kb16 (32)][nf (64)][lane (32)].
__device__ uint4 g_Bfrag[32 * 64 * 32];   // rec_kernel R
__device__ uint4 g_Wfrag[32 * 64 * 32];   // input kernel W

// h in A-fragment order (m16n8k16 bf16), hi/lo split. Per lane 8 u32:
// regs 0..3 = hi {a0..a3}, regs 4..7 = lo. Ping-pong.
// Index: ((mf*32 + kb16)*32 + lane)*8 + reg.
__device__ uint32_t g_Afrag[2][(size_t)64 * 32 * 32 * 8];

// Grid-barrier flags (one per inter-step barrier), zeroed every launch
__device__ unsigned g_flag[128];

// ---------------------------------------------------------------------------
// Helpers
// ---------------------------------------------------------------------------
__device__ __forceinline__ void split2(float a, float b, uint32_t& hp, uint32_t& lp)
{
    __nv_bfloat16 ah = __float2bfloat16_rn(a);
    __nv_bfloat16 bh = __float2bfloat16_rn(b);
    float ar = a - __bfloat162float(ah);
    float br = b - __bfloat162float(bh);
    __nv_bfloat16 al = __float2bfloat16_rn(ar);
    __nv_bfloat16 bl = __float2bfloat16_rn(br);
    hp = (uint32_t)__bfloat16_as_ushort(ah) | ((uint32_t)__bfloat16_as_ushort(bh) << 16);
    lp = (uint32_t)__bfloat16_as_ushort(al) | ((uint32_t)__bfloat16_as_ushort(bl) << 16);
}

__device__ __forceinline__ void mma16(float* c, const uint32_t* a, const uint32_t* b)
{
    asm volatile(
        "mma.sync.aligned.m16n8k16.row.col.f32.bf16.bf16.f32 "
        "{%0,%1,%2,%3}, {%4,%5,%6,%7}, {%8,%9}, {%0,%1,%2,%3};"
        : "+f"(c[0]), "+f"(c[1]), "+f"(c[2]), "+f"(c[3])
        : "r"(a[0]), "r"(a[1]), "r"(a[2]), "r"(a[3]), "r"(b[0]), "r"(b[1]));
}

// bf16x3: d += hi*lo' + lo*hi' + hi*hi'
__device__ __forceinline__ void mma3x(float* c,
                                      const uint32_t* ah, const uint32_t* al,
                                      const uint32_t* bh, const uint32_t* bl)
{
    mma16(c, ah, bl);
    mma16(c, al, bh);
    mma16(c, ah, bh);
}

__device__ __forceinline__ void cp16(uint32_t saddr, const void* gptr)
{
    asm volatile("cp.async.cg.shared.global [%0], [%1], 16;\n"
                 :: "r"(saddr), "l"(gptr) : "memory");
}
__device__ __forceinline__ uint32_t saddr_of(const void* p)
{
    return (uint32_t)__cvta_generic_to_shared(p);
}

// ---------------------------------------------------------------------------
// prep: 512x512 row-major fp32 -> B-fragment order, bf16 hi/lo split
// ---------------------------------------------------------------------------
__global__ void prep_frag_512(const float* __restrict__ M, uint4* __restrict__ dst)
{
    int id = blockIdx.x * 256 + threadIdx.x;      // < 65536
    int lane = id & 31, nf = (id >> 5) & 63, kb = id >> 11;
    int tg = lane & 3, n = nf * 8 + (lane >> 2);
    int k0 = kb * 16 + 2 * tg;
    float e00 = M[(size_t)k0 * 512 + n];
    float e01 = M[(size_t)(k0 + 1) * 512 + n];
    float e10 = M[(size_t)(k0 + 8) * 512 + n];
    float e11 = M[(size_t)(k0 + 9) * 512 + n];
    uint32_t bh0, bl0, bh1, bl1;
    split2(e00, e01, bh0, bl0);
    split2(e10, e11, bh1, bl1);
    dst[id] = make_uint4(bh0, bh1, bl0, bl1);
}

// ---------------------------------------------------------------------------
// Proj GEMM (bf16x3): g_proj[v,n] = sum_e emb[v,e]*W[e,n] + bias[n]
// CTA 128x64, 8 warps (warp 32x32), K-tile 16, double-buffered.
// W comes pre-split from g_Wfrag via cp.async; A (emb) split in-kernel.
// ---------------------------------------------------------------------------
__global__ void __launch_bounds__(256)
gemm_proj_bf16(const float* __restrict__ emb, const float* __restrict__ bias)
{
    __shared__ __align__(16) uint32_t sA[2][8][32][12]; // [buf][mf][lane][hi4|lo4|pad4]
    __shared__ __align__(16) uint4    sB[2][8][32];     // [buf][nf][lane]

    const int tid  = threadIdx.x;
    const int m0   = blockIdx.x * 128;
    const int by   = blockIdx.y;
    const int lane = tid & 31;
    const int warp = tid >> 5;
    const int wm   = warp & 3;
    const int wn   = warp >> 2;

    // A loader: 2 threads per row, 8 consecutive k each
    const int ar  = tid >> 1;
    const int kh  = (tid & 1) * 8;
    const int arow = min(m0 + ar, V_ - 1);
    const float* aptr = emb + (size_t)arow * E_ + kh;
    const int r16    = ar & 15;
    const int a_mf   = ar >> 4;
    const int a_lnb  = (r16 & 7) << 2;
    const int a_reg  = (r16 >> 3) | ((kh >> 3) << 1);

    const int b_nf = tid >> 5;
    const int b_ln = tid & 31;

    float acc[2][4][4];
#pragma unroll
    for (int i = 0; i < 2; i++)
#pragma unroll
        for (int j = 0; j < 4; j++)
#pragma unroll
            for (int q = 0; q < 4; q++) acc[i][j][q] = 0.f;

    auto cpB = [&](int kt, int buf) {
        const uint4* gp = g_Wfrag + (((size_t)kt * 64) + by * 8 + b_nf) * 32 + b_ln;
        cp16(saddr_of(&sB[buf][b_nf][b_ln]), gp);
    };
    auto storeA = [&](int buf, float4 a0, float4 a1) {
        float v[8] = {a0.x, a0.y, a0.z, a0.w, a1.x, a1.y, a1.z, a1.w};
#pragma unroll
        for (int p = 0; p < 4; p++) {
            uint32_t hp, lp;
            split2(v[2 * p], v[2 * p + 1], hp, lp);
            sA[buf][a_mf][a_lnb + p][a_reg]     = hp;
            sA[buf][a_mf][a_lnb + p][a_reg + 4] = lp;
        }
    };

    float4 a0 = *reinterpret_cast<const float4*>(aptr);
    float4 a1 = *reinterpret_cast<const float4*>(aptr + 4);
    cpB(0, 0);
    asm volatile("cp.async.commit_group;\n" ::: "memory");
    storeA(0, a0, a1);
    asm volatile("cp.async.wait_group 0;\n" ::: "memory");
    __syncthreads();

    for (int kt = 0; kt < 32; kt++) {
        int buf = kt & 1;
        float4 a0n, a1n;
        if (kt + 1 < 32) {
            a0n = *reinterpret_cast<const float4*>(aptr + (kt + 1) * 16);
            a1n = *reinterpret_cast<const float4*>(aptr + (kt + 1) * 16 + 4);
            cpB(kt + 1, buf ^ 1);
        }
        asm volatile("cp.async.commit_group;\n" ::: "memory");

        uint4 ah[2], al[2];
#pragma unroll
        for (int i = 0; i < 2; i++) {
            ah[i] = *reinterpret_cast<const uint4*>(&sA[buf][wm * 2 + i][lane][0]);
            al[i] = *reinterpret_cast<const uint4*>(&sA[buf][wm * 2 + i][lane][4]);
        }
#pragma unroll
        for (int j = 0; j < 4; j++) {
            uint4 bq = sB[buf][wn * 4 + j][lane];
#pragma unroll
            for (int i = 0; i < 2; i++)
                mma3x(acc[i][j], &ah[i].x, &al[i].x, &bq.x, &bq.z);
        }

        if (kt + 1 < 32) storeA(buf ^ 1, a0n, a1n);
        asm volatile("cp.async.wait_group 0;\n" ::: "memory");
        __syncthreads();
    }

    // Epilogue: + bias, store fp32 (guard V)
    const int g = lane >> 2, tg = lane & 3;
#pragma unroll
    for (int i = 0; i < 2; i++) {
        int row = m0 + (wm * 2 + i) * 16 + g;
#pragma unroll
        for (int j = 0; j < 4; j++) {
            int col = by * 64 + (wn * 4 + j) * 8 + tg * 2;
            float b0 = bias[col], b1 = bias[col + 1];
            if (row < V_) {
                float2 o0 = {acc[i][j][0] + b0, acc[i][j][1] + b1};
                *reinterpret_cast<float2*>(g_proj + (size_t)row * U_ + col) = o0;
            }
            if (row + 8 < V_) {
                float2 o1 = {acc[i][j][2] + b0, acc[i][j][3] + b1};
                *reinterpret_cast<float2*>(g_proj + (size_t)(row + 8) * U_ + col) = o1;
            }
        }
    }
}

// ---------------------------------------------------------------------------
// zero flags (every launch, before the persistent kernel)
// ---------------------------------------------------------------------------
__global__ void zero_flags()
{
    if (threadIdx.x < 128) g_flag[threadIdx.x] = 0;
}

// ---------------------------------------------------------------------------
// Persistent recurrence: 128 CTAs (16 bm x 8 bn), 128 threads (4 warps, 32x32).
// R slice (64 cols x 512 k, split) resident in SMEM; h streamed via cp.async;
// xk gathered from g_proj by token in the epilogue; software grid barrier.
// ---------------------------------------------------------------------------
#define SA_IDX(s, mf, kbL, ln, w) \
    ((((((s) * 4 + (mf)) * 2 + (kbL)) * 32 + (ln)) * 12) + (w))

extern __shared__ uint8_t smem_dyn[];

__global__ void __launch_bounds__(128)
rnn_persistent(const int* __restrict__ tokens)
{
    uint4*    sBres = reinterpret_cast<uint4*>(smem_dyn);              // 8192 uint4
    uint32_t* sA    = reinterpret_cast<uint32_t*>(smem_dyn + 131072);  // 3 stages

    const int tid  = threadIdx.x;
    const int lane = tid & 31;
    const int warp = tid >> 5;      // 0..3
    const int wm   = warp & 1;      // 2 mf each
    const int wn   = warp >> 1;     // 4 nf each
    const int cta  = blockIdx.x;    // 0..127
    const int bm   = cta & 15;
    const int bn   = cta >> 4;
    const int m0f  = bm * 4;
    const int n0f  = bn * 8;

    // ---- Load resident B slice (R columns n0f*8 .. +64), 64 cp16/thread ----
    for (int i = 0; i < 64; i++) {
        int s4 = tid + i * 128;                 // 0..8191
        int ln = s4 & 31, nfL = (s4 >> 5) & 7, kb = s4 >> 8;
        const uint4* gp = g_Bfrag + (size_t)kb * 2048 + (n0f + nfL) * 32 + ln;
        cp16(saddr_of(sBres + s4), gp);
    }
    asm volatile("cp.async.commit_group;\n" ::: "memory");
    asm volatile("cp.async.wait_group 0;\n" ::: "memory");
    __syncthreads();

    const int g  = lane >> 2, tg = lane & 3;

    // Epilogue: h = tanh(acc + proj[tok_t]), write split A-frags to Aout
    auto epilogue = [&](int t, float (*acc)[4][4], uint32_t* Aout) {
#pragma unroll
        for (int i = 0; i < 2; i++) {
            const int r0  = bm * 64 + (wm * 2 + i) * 16 + g;
            const int mfg = bm * 4 + wm * 2 + i;
            const int tok0 = tokens[r0 * T_ + t];
            const int tok1 = tokens[(r0 + 8) * T_ + t];
#pragma unroll
            for (int j = 0; j < 4; j++) {
                const int nf = n0f + wn * 4 + j;
                const int c  = nf * 8 + tg * 2;
                float2 x0 = *reinterpret_cast<const float2*>(g_proj + (size_t)tok0 * U_ + c);
                float2 x1 = *reinterpret_cast<const float2*>(g_proj + (size_t)tok1 * U_ + c);
                float h00 = tanhf(acc[i][j][0] + x0.x);
                float h01 = tanhf(acc[i][j][1] + x0.y);
                float h10 = tanhf(acc[i][j][2] + x1.x);
                float h11 = tanhf(acc[i][j][3] + x1.y);
                uint32_t hp0, lp0, hp1, lp1;
                split2(h00, h01, hp0, lp0);
                split2(h10, h11, hp1, lp1);
                size_t base = ((((size_t)mfg * 32) + (nf >> 1)) * 32 + ((g << 2) | tg)) * 8;
                int rs = (nf & 1) << 1;
                Aout[base + rs]     = hp0;
                Aout[base + rs + 1] = hp1;
                Aout[base + rs + 4] = lp0;
                Aout[base + rs + 5] = lp1;
            }
        }
    };

    // ---- t = 0: h = tanh(proj[tok_0])  (h0 == 0) ----
    {
        float z[2][4][4];
#pragma unroll
        for (int i = 0; i < 2; i++)
#pragma unroll
            for (int j = 0; j < 4; j++)
#pragma unroll
                for (int q = 0; q < 4; q++) z[i][j][q] = 0.f;
        epilogue(0, z, g_Afrag[0]);
    }

    // grid barrier helper
    auto gbar = [&](int i) {
        __syncthreads();
        if (tid == 0) {
            __threadfence();
            atomicAdd(&g_flag[i], 1u);
            while (*(volatile unsigned*)&g_flag[i] < 128u) {}
        }
        __syncthreads();
    };

    gbar(0);

    // A-stage copy duty: 4 cp16/thread/stage
    auto issue = [&](int kt2, const uint32_t* Ag) {
        if (kt2 < 16) {
            const int s   = kt2 % 3;
            const int kb0 = kt2 << 1;
#pragma unroll
            for (int i = 0; i < 4; i++) {
                int s6  = (tid >> 5) + i * 4;     // 0..15
                int hl  = s6 & 1;
                int kbL = (s6 >> 1) & 1;
                int mf  = s6 >> 2;
                const uint32_t* gp = Ag +
                    ((((size_t)(m0f + mf) * 32) + kb0 + kbL) * 32 + lane) * 8 + (hl << 2);
                cp16(saddr_of(&sA[SA_IDX(s, mf, kbL, lane, hl << 2)]), gp);
            }
        }
        asm volatile("cp.async.commit_group;\n" ::: "memory");
    };

    for (int t = 1; t < T_; t++) {
        const uint32_t* Ag = g_Afrag[(t - 1) & 1];
        uint32_t*       Ao = g_Afrag[t & 1];

        float acc[2][4][4];
#pragma unroll
        for (int i = 0; i < 2; i++)
#pragma unroll
            for (int j = 0; j < 4; j++)
#pragma unroll
                for (int q = 0; q < 4; q++) acc[i][j][q] = 0.f;

        issue(0, Ag);
        issue(1, Ag);

        for (int kt = 0; kt < 16; kt++) {
            asm volatile("cp.async.wait_group 1;\n" ::: "memory");
            __syncthreads();
            issue(kt + 2, Ag);
            const int s = kt % 3;
#pragma unroll
            for (int kbL = 0; kbL < 2; kbL++) {
                uint4 ah[2], al[2];
#pragma unroll
                for (int i = 0; i < 2; i++) {
                    ah[i] = *reinterpret_cast<const uint4*>(&sA[SA_IDX(s, wm * 2 + i, kbL, lane, 0)]);
                    al[i] = *reinterpret_cast<const uint4*>(&sA[SA_IDX(s, wm * 2 + i, kbL, lane, 4)]);
                }
#pragma unroll
                for (int j = 0; j < 4; j++) {
                    uint4 bq = sBres[(size_t)(kt * 2 + kbL) * 256 + (wn * 4 + j) * 32 + lane];
#pragma unroll
                    for (int i = 0; i < 2; i++)
                        mma3x(acc[i][j], &ah[i].x, &al[i].x, &bq.x, &bq.z);
                }
            }
        }

        epilogue(t, acc, Ao);
        if (t < T_ - 1) gbar(t);
    }
}

// ---------------------------------------------------------------------------
// Final: out[b] = sigmoid(h[b] . fc_w + fc_b), h read from fragment layout
// ---------------------------------------------------------------------------
__global__ void final_frag(const float* __restrict__ fc_w,
                           const float* __restrict__ fc_b,
                           float* __restrict__ out)
{
    int gw = (blockIdx.x * blockDim.x + threadIdx.x) >> 5;
    int lane = threadIdx.x & 31;
    if (gw >= B_) return;
    const uint32_t* A = g_Afrag[1];     // t=79 writes buffer 1
    int mf = gw >> 4, r16 = gw & 15;
    float s = 0.f;
    for (int u = lane; u < U_; u += 32) {
        int kb = u >> 4, k = u & 15;
        int li  = ((r16 & 7) << 2) | ((k & 7) >> 1);
        int reg = (r16 >> 3) | ((k >> 3) << 1);
        size_t base = ((((size_t)mf * 32) + kb) * 32 + li) * 8;
        uint32_t hw = A[base + reg], lw = A[base + reg + 4];
        uint16_t hb = (k & 1) ? (uint16_t)(hw >> 16) : (uint16_t)hw;
        uint16_t lb = (k & 1) ? (uint16_t)(lw >> 16) : (uint16_t)lw;
        float v = __bfloat162float(__ushort_as_bfloat16(hb))
                + __bfloat162float(__ushort_as_bfloat16(lb));
        s = fmaf(v, fc_w[u], s);
    }
#pragma unroll
    for (int o = 16; o; o >>= 1) s += __shfl_xor_sync(0xffffffffu, s, o);
    if (lane == 0) out[gw] = 1.f / (1.f + expf(-(s + fc_b[0])));
}

// ---------------------------------------------------------------------------
// Launch
// ---------------------------------------------------------------------------
extern "C" void kernel_launch(void* const* d_in, const int* in_sizes, int n_in,
                              void* d_out, int out_size)
{
    const int*   tokens     = (const int*)  d_in[0];   // [B, T]
    const float* emb        = (const float*)d_in[1];   // [V, E]
    const float* kernel     = (const float*)d_in[2];   // [E, U]
    const float* rec_kernel = (const float*)d_in[3];   // [U, U]
    const float* bias       = (const float*)d_in[4];   // [U]
    const float* fc_w       = (const float*)d_in[5];   // [U, 1]
    const float* fc_b       = (const float*)d_in[6];   // [1]
    float* out = (float*)d_out;                        // [B, 1]

    static bool attr_set = false;
    if (!attr_set) {
        cudaFuncSetAttribute(rnn_persistent,
                             cudaFuncAttributeMaxDynamicSharedMemorySize, 167936);
        attr_set = true;
    }

    // 0) Pre-split weights into fragment order (once each)
    uint4* dB; cudaGetSymbolAddress((void**)&dB, g_Bfrag);
    uint4* dW; cudaGetSymbolAddress((void**)&dW, g_Wfrag);
    prep_frag_512<<<256, 256>>>(rec_kernel, dB);
    prep_frag_512<<<256, 256>>>(kernel, dW);

    // 1) Vocabulary projection table: proj = emb @ W + bias  (50000 x 512)
    dim3 g1((V_ + 127) / 128, U_ / 64);   // (391, 8)
    gemm_proj_bf16<<<g1, 256>>>(emb, bias);

    // 2) Reset grid-barrier flags (required for every graph replay)
    zero_flags<<<1, 128>>>();

    // 3) Persistent recurrence: all 80 timesteps in one kernel
    rnn_persistent<<<128, 128, 167936>>>(tokens);

    // 4) Classifier head + sigmoid
    final_frag<<<B_ / 8, 256>>>(fc_w, fc_b, out);
}